// round 2
// baseline (speedup 1.0000x reference)
#include <cuda_runtime.h>
#include <math.h>

// scratch (static __device__ — no allocations)
__device__ float g_h1[(size_t)512 * 32 * 144];
__device__ float g_h4[(size_t)512 * 64 * 144];
__device__ float g_xz[(size_t)512 * 64 * 576];

__device__ __forceinline__ float d4(float4 a, float4 b) {
    return a.x * b.x + a.y * b.y + a.z * b.z + a.w * b.w;
}

// ============ kernel 1: conv1(200->32,3x3,pad1)+BN+ReLU ============
__global__ void __launch_bounds__(288) k_front(
    const float* __restrict__ x, const float* __restrict__ w1,
    const float* __restrict__ b1, const float* __restrict__ g1,
    const float* __restrict__ be1, const float* __restrict__ m1,
    const float* __restrict__ v1)
{
    __shared__ float xs[8 * 144];
    __shared__ float ws[8 * 288];
    int bi = blockIdx.x, tid = threadIdx.x;
    int quad = tid % 36, ocg = tid / 36;
    int py = quad / 3, px0 = (quad % 3) * 4;
    float acc[4][4] = {};
    const float* xb = x + (size_t)bi * 28800;
    for (int c0 = 0; c0 < 200; c0 += 8) {
        __syncthreads();
        for (int i = tid; i < 8 * 144; i += 288) xs[i] = xb[c0 * 144 + i];
        for (int i = tid; i < 8 * 288; i += 288) {
            int ic = i / 288, r = i % 288;
            ws[i] = w1[(r / 9) * 1800 + (c0 + ic) * 9 + (r % 9)];
        }
        __syncthreads();
#pragma unroll 1
        for (int ic = 0; ic < 8; ic++) {
            float xv[3][6];
#pragma unroll
            for (int rr = 0; rr < 3; rr++)
#pragma unroll
                for (int cc = 0; cc < 6; cc++) {
                    int yy = py + rr - 1, xx = px0 + cc - 1;
                    xv[rr][cc] = (yy >= 0 && yy < 12 && xx >= 0 && xx < 12)
                                     ? xs[ic * 144 + yy * 12 + xx] : 0.f;
                }
#pragma unroll
            for (int o = 0; o < 4; o++) {
                const float* wr = &ws[ic * 288 + (ocg * 4 + o) * 9];
                float a0 = wr[0], a1 = wr[1], a2 = wr[2], a3 = wr[3], a4 = wr[4],
                      a5 = wr[5], a6 = wr[6], a7 = wr[7], a8 = wr[8];
#pragma unroll
                for (int q = 0; q < 4; q++)
                    acc[o][q] += a0 * xv[0][q] + a1 * xv[0][q + 1] + a2 * xv[0][q + 2]
                               + a3 * xv[1][q] + a4 * xv[1][q + 1] + a5 * xv[1][q + 2]
                               + a6 * xv[2][q] + a7 * xv[2][q + 1] + a8 * xv[2][q + 2];
            }
        }
    }
#pragma unroll
    for (int o = 0; o < 4; o++) {
        int oc = ocg * 4 + o;
        float inv = g1[oc] * rsqrtf(v1[oc] + 1e-5f);
        float sh = (b1[oc] - m1[oc]) * inv + be1[oc];
        float4 v;
        v.x = fmaxf(acc[o][0] * inv + sh, 0.f);
        v.y = fmaxf(acc[o][1] * inv + sh, 0.f);
        v.z = fmaxf(acc[o][2] * inv + sh, 0.f);
        v.w = fmaxf(acc[o][3] * inv + sh, 0.f);
        *(float4*)&g_h1[(size_t)bi * 4608 + oc * 144 + py * 12 + px0] = v;
    }
}

// ============ kernel 2: conv2+BN+ReLU -> we -> wc2 -> in_w ============
// arena (floats): stage[0,9216) (img at [4608,9216) in phase A),
// h2[9216,18688) stride 148, h3[18688,28160) stride 148, h4 overlays h2.
__global__ void __launch_bounds__(288, 2) k_mid(
    const float* __restrict__ w2, const float* __restrict__ b2,
    const float* __restrict__ g2, const float* __restrict__ be2,
    const float* __restrict__ m2, const float* __restrict__ v2,
    const float* __restrict__ wc2, const float* __restrict__ bc2,
    const float* __restrict__ we, const float* __restrict__ bee,
    const float* __restrict__ in_w)
{
    extern __shared__ float sm[];
    float* stage = sm;
    float* img = sm + 4608;
    float* h2 = sm + 9216;
    float* h3 = sm + 18688;
    float* h4 = sm + 9216;
    int bi = blockIdx.x, tid = threadIdx.x;

    // ---- phase A: conv2 ----
    for (int i = tid; i < 4608; i += 288) img[i] = g_h1[(size_t)bi * 4608 + i];
    {
        int quad = tid % 36, ocg = tid / 36;
        int py = quad / 3, px0 = (quad % 3) * 4;
        float acc[8][4] = {};
        for (int c0 = 0; c0 < 32; c0 += 8) {
            __syncthreads();
            for (int i = tid; i < 8 * 576; i += 288) {
                int ic = i / 576, r = i % 576;
                stage[i] = w2[(r / 9) * 288 + (c0 + ic) * 9 + (r % 9)];
            }
            __syncthreads();
#pragma unroll 1
            for (int ic = 0; ic < 8; ic++) {
                float xv[3][6];
#pragma unroll
                for (int rr = 0; rr < 3; rr++)
#pragma unroll
                    for (int cc = 0; cc < 6; cc++) {
                        int yy = py + rr - 1, xx = px0 + cc - 1;
                        xv[rr][cc] = (yy >= 0 && yy < 12 && xx >= 0 && xx < 12)
                                         ? img[(c0 + ic) * 144 + yy * 12 + xx] : 0.f;
                    }
#pragma unroll
                for (int o = 0; o < 8; o++) {
                    const float* wr = &stage[ic * 576 + (ocg * 8 + o) * 9];
                    float a0 = wr[0], a1 = wr[1], a2 = wr[2], a3 = wr[3], a4 = wr[4],
                          a5 = wr[5], a6 = wr[6], a7 = wr[7], a8 = wr[8];
#pragma unroll
                    for (int q = 0; q < 4; q++)
                        acc[o][q] += a0 * xv[0][q] + a1 * xv[0][q + 1] + a2 * xv[0][q + 2]
                                   + a3 * xv[1][q] + a4 * xv[1][q + 1] + a5 * xv[1][q + 2]
                                   + a6 * xv[2][q] + a7 * xv[2][q + 1] + a8 * xv[2][q + 2];
                }
            }
        }
#pragma unroll
        for (int o = 0; o < 8; o++) {
            int oc = ocg * 8 + o;
            float inv = g2[oc] * rsqrtf(v2[oc] + 1e-5f);
            float sh = (b2[oc] - m2[oc]) * inv + be2[oc];
#pragma unroll
            for (int q = 0; q < 4; q++)
                h2[oc * 148 + py * 12 + px0 + q] = fmaxf(acc[o][q] * inv + sh, 0.f);
        }
    }

    // ---- phase B: h3 = h2 @ we^T + bee ----
    for (int i0 = 0; i0 < 144; i0 += 64) {
        int ci = (144 - i0) < 64 ? (144 - i0) : 64;
        __syncthreads();
        for (int i = tid; i < ci * 144; i += 288)
            stage[i] = we[(i0 + i / 144) * 144 + (i % 144)];
        __syncthreads();
        int nt = 16 * (ci / 4);
        for (int tile = tid; tile < nt; tile += 288) {
            int t0 = (tile & 15) * 4, ii0 = (tile >> 4) * 4;
            float a[4][4] = {};
            for (int j = 0; j < 144; j += 4) {
                float4 hv[4], wv[4];
#pragma unroll
                for (int r = 0; r < 4; r++) hv[r] = *(const float4*)&h2[(t0 + r) * 148 + j];
#pragma unroll
                for (int c = 0; c < 4; c++) wv[c] = *(const float4*)&stage[(ii0 + c) * 144 + j];
#pragma unroll
                for (int r = 0; r < 4; r++)
#pragma unroll
                    for (int c = 0; c < 4; c++) a[r][c] += d4(hv[r], wv[c]);
            }
#pragma unroll
            for (int r = 0; r < 4; r++)
#pragma unroll
                for (int c = 0; c < 4; c++)
                    h3[(t0 + r) * 148 + i0 + ii0 + c] = a[r][c] + bee[i0 + ii0 + c];
        }
    }

    // ---- phase C: h4 = wc2-mix(h3) + bc2 (token mixing) ----
    __syncthreads();
    for (int i = tid; i < 4096; i += 288) stage[i] = wc2[i];
    __syncthreads();
    for (int idx = tid; idx < 9216; idx += 288) {
        int lo = idx / 144, p = idx - lo * 144;
        float s = 0.f;
#pragma unroll 8
        for (int li = 0; li < 64; li++) s += h3[li * 148 + p] * stage[lo * 64 + li];
        s += bc2[lo];
        h4[lo * 148 + p] = s;
        g_h4[(size_t)bi * 9216 + idx] = s;
    }

    // ---- phase D: xz = h4 @ in_w^T -> g_xz ----
    for (int o0 = 0; o0 < 576; o0 += 64) {
        __syncthreads();
        for (int i = tid; i < 64 * 144; i += 288)
            stage[i] = in_w[(o0 + i / 144) * 144 + (i % 144)];
        __syncthreads();
        for (int tile = tid; tile < 256; tile += 288) {
            int t0 = (tile & 15) * 4, oo0 = (tile >> 4) * 4;
            float a[4][4] = {};
            for (int j = 0; j < 144; j += 4) {
                float4 hv[4], wv[4];
#pragma unroll
                for (int r = 0; r < 4; r++) hv[r] = *(const float4*)&h4[(t0 + r) * 148 + j];
#pragma unroll
                for (int c = 0; c < 4; c++) wv[c] = *(const float4*)&stage[(oo0 + c) * 144 + j];
#pragma unroll
                for (int r = 0; r < 4; r++)
#pragma unroll
                    for (int c = 0; c < 4; c++) a[r][c] += d4(hv[r], wv[c]);
            }
#pragma unroll
            for (int r = 0; r < 4; r++) {
                float4 st = {a[r][0], a[r][1], a[r][2], a[r][3]};
                *(float4*)&g_xz[(size_t)bi * 36864 + (t0 + r) * 576 + o0 + oo0] = st;
            }
        }
    }
}

// ============ kernel 3: mamba + residual + wc3 + BN + ReLU ============
// arena: uY[0,18432) (xm -> u -> gated y), dbl[18432,21504), rS overlays dbl [18432,27648)
__global__ void __launch_bounds__(288, 2) k_mamba(
    const float* __restrict__ convd_w, const float* __restrict__ convd_b,
    const float* __restrict__ xproj_w, const float* __restrict__ dtproj_w,
    const float* __restrict__ dtproj_b, const float* __restrict__ A_log,
    const float* __restrict__ Dp, const float* __restrict__ out_w,
    const float* __restrict__ wc3, const float* __restrict__ bc3,
    const float* __restrict__ g3, const float* __restrict__ be3,
    const float* __restrict__ m3, const float* __restrict__ v3,
    float* __restrict__ out)
{
    extern __shared__ float sm[];
    float* uY = sm;
    float* dbl = sm + 18432;
    float* rS = sm + 18432;
    int bi = blockIdx.x, c = threadIdx.x;
    const float* xzb = g_xz + (size_t)bi * 36864;

    for (int i = c; i < 18432; i += 288) {
        int t = i / 288, ch = i - t * 288;
        uY[i] = xzb[t * 576 + ch];
    }
    __syncthreads();

    // depthwise causal conv (DC=4, left pad 3) + SiLU, in place, thread=channel
    {
        float cw0 = convd_w[c * 4], cw1 = convd_w[c * 4 + 1],
              cw2 = convd_w[c * 4 + 2], cw3 = convd_w[c * 4 + 3];
        float cb = convd_b[c];
        float p0 = 0.f, p1 = 0.f, p2 = 0.f;
        for (int t = 0; t < 64; t++) {
            float xt = uY[t * 288 + c];
            float s = cw0 * p0 + cw1 * p1 + cw2 * p2 + cw3 * xt + cb;
            s = s / (1.f + __expf(-s));
            uY[t * 288 + c] = s;
            p0 = p1; p1 = p2; p2 = xt;
        }
    }
    __syncthreads();

    // xproj: dbl[t][0..40] = u[t] . xproj_w[j]
    for (int o = c; o < 64 * 41; o += 288) {
        int t = o / 41, j = o - t * 41;
        const float4* u4 = (const float4*)&uY[t * 288];
        const float4* w4 = (const float4*)&xproj_w[j * 288];
        float s = 0.f;
#pragma unroll 8
        for (int k = 0; k < 72; k++) {
            float4 a = u4[k], w = __ldg(&w4[k]);
            s += a.x * w.x + a.y * w.y + a.z * w.z + a.w * w.w;
        }
        dbl[t * 48 + j] = s;
    }
    __syncthreads();

    // selective scan + gate (thread=channel, 16 states in regs)
    {
        float dtw[9], A[16], h[16];
#pragma unroll
        for (int r = 0; r < 9; r++) dtw[r] = dtproj_w[c * 9 + r];
        float dtb = dtproj_b[c];
#pragma unroll
        for (int n = 0; n < 16; n++) { A[n] = -__expf(A_log[c * 16 + n]); h[n] = 0.f; }
        float dpc = Dp[c];
        for (int t = 0; t < 64; t++) {
            float zv = xzb[t * 576 + 288 + c];
            float dt = dtb;
#pragma unroll
            for (int r = 0; r < 9; r++) dt += dbl[t * 48 + r] * dtw[r];
            float delta = fmaxf(dt, 0.f) + log1pf(__expf(-fabsf(dt)));
            float u = uY[t * 288 + c];
            float dlu = delta * u;
            float y = 0.f;
#pragma unroll
            for (int n = 0; n < 16; n++) {
                float e = __expf(delta * A[n]);
                h[n] = h[n] * e + dlu * dbl[t * 48 + 9 + n];
                y += h[n] * dbl[t * 48 + 25 + n];
            }
            float sz = zv / (1.f + __expf(-zv));
            uY[t * 288 + c] = (y + u * dpc) * sz;
        }
    }
    __syncthreads();

    // out-proj + residual -> rS
    for (int tile = c; tile < 576; tile += 288) {
        int t0 = (tile & 15) * 4, i0 = (tile >> 4) * 4;
        float a[4][4] = {};
        const float4* ow = (const float4*)out_w;
        for (int k = 0; k < 72; k++) {
            float4 yv[4], wv[4];
#pragma unroll
            for (int r = 0; r < 4; r++) yv[r] = *(const float4*)&uY[(t0 + r) * 288 + k * 4];
#pragma unroll
            for (int cc = 0; cc < 4; cc++) wv[cc] = __ldg(&ow[(i0 + cc) * 72 + k]);
#pragma unroll
            for (int r = 0; r < 4; r++)
#pragma unroll
                for (int cc = 0; cc < 4; cc++) a[r][cc] += d4(yv[r], wv[cc]);
        }
#pragma unroll
        for (int r = 0; r < 4; r++) {
            float4 res = __ldg((const float4*)&g_h4[(size_t)bi * 9216 + (t0 + r) * 144 + i0]);
            float4 st = {a[r][0] + res.x, a[r][1] + res.y, a[r][2] + res.z, a[r][3] + res.w};
            *(float4*)&rS[(t0 + r) * 144 + i0] = st;
        }
    }
    __syncthreads();

    // wc3 (64->32 token mix) + BN + ReLU -> out
    for (int idx = c; idx < 4608; idx += 288) {
        int oc = idx / 144, p = idx - oc * 144;
        float s = 0.f;
#pragma unroll 8
        for (int li = 0; li < 64; li++) s += rS[li * 144 + p] * __ldg(&wc3[oc * 64 + li]);
        float inv = g3[oc] * rsqrtf(v3[oc] + 1e-5f);
        float val = (s + bc3[oc]) * inv + be3[oc] - m3[oc] * inv;
        out[(size_t)bi * 4608 + idx] = fmaxf(val, 0.f);
    }
}

extern "C" void kernel_launch(void* const* d_in, const int* in_sizes, int n_in,
                              void* d_out, int out_size)
{
    const float* x       = (const float*)d_in[0];
    const float* w1      = (const float*)d_in[1];
    const float* b1      = (const float*)d_in[2];
    const float* g1      = (const float*)d_in[3];
    const float* be1     = (const float*)d_in[4];
    const float* m1      = (const float*)d_in[5];
    const float* v1      = (const float*)d_in[6];
    const float* w2      = (const float*)d_in[7];
    const float* b2      = (const float*)d_in[8];
    const float* g2      = (const float*)d_in[9];
    const float* be2     = (const float*)d_in[10];
    const float* m2      = (const float*)d_in[11];
    const float* v2      = (const float*)d_in[12];
    const float* wc2     = (const float*)d_in[13];
    const float* bc2     = (const float*)d_in[14];
    const float* we      = (const float*)d_in[15];
    const float* bee     = (const float*)d_in[16];
    const float* in_w    = (const float*)d_in[17];
    const float* convd_w = (const float*)d_in[18];
    const float* convd_b = (const float*)d_in[19];
    const float* xproj_w = (const float*)d_in[20];
    const float* dtproj_w= (const float*)d_in[21];
    const float* dtproj_b= (const float*)d_in[22];
    const float* A_log   = (const float*)d_in[23];
    const float* Dp      = (const float*)d_in[24];
    const float* out_w   = (const float*)d_in[25];
    const float* wc3     = (const float*)d_in[26];
    const float* bc3     = (const float*)d_in[27];
    const float* g3      = (const float*)d_in[28];
    const float* be3     = (const float*)d_in[29];
    const float* m3      = (const float*)d_in[30];
    const float* v3      = (const float*)d_in[31];

    int B = in_sizes[0] / 28800;

    cudaFuncSetAttribute(k_mid, cudaFuncAttributeMaxDynamicSharedMemorySize, 112640);
    cudaFuncSetAttribute(k_mamba, cudaFuncAttributeMaxDynamicSharedMemorySize, 110592);

    k_front<<<B, 288>>>(x, w1, b1, g1, be1, m1, v1);
    k_mid<<<B, 288, 112640>>>(w2, b2, g2, be2, m2, v2, wc2, bc2, we, bee, in_w);
    k_mamba<<<B, 288, 110592>>>(convd_w, convd_b, xproj_w, dtproj_w, dtproj_b,
                                A_log, Dp, out_w, wc3, bc3, g3, be3, m3, v3,
                                (float*)d_out);
}

// round 3
// speedup vs baseline: 1.2664x; 1.2664x over previous
#include <cuda_runtime.h>
#include <math.h>

// scratch (static __device__ — no allocations)
__device__ float g_h1[(size_t)512 * 32 * 144];
__device__ float g_h4[(size_t)512 * 64 * 144];
__device__ float g_xz[(size_t)512 * 64 * 576];

__device__ __forceinline__ float d4(float4 a, float4 b) {
    return a.x * b.x + a.y * b.y + a.z * b.z + a.w * b.w;
}

// ============ kernel 1: conv1(200->32,3x3,pad1)+BN+ReLU ============
// padded 14x14 input windows (no border predication), weights staged
// as [ic][tap][oc] for float4 reads.
__global__ void __launch_bounds__(288, 3) k_front(
    const float* __restrict__ x, const float* __restrict__ w1,
    const float* __restrict__ b1, const float* __restrict__ g1,
    const float* __restrict__ be1, const float* __restrict__ m1,
    const float* __restrict__ v1)
{
    __shared__ float xs[8 * 196];    // 8 ic x 14x14 padded
    __shared__ float ws[8 * 288];    // 8 ic x 9 tap x 32 oc
    int bi = blockIdx.x, tid = threadIdx.x;
    int quad = tid % 36, ocg = tid / 36;
    int py = quad / 3, px0 = (quad % 3) * 4;
    float acc[4][4] = {};
    const float* xb = x + (size_t)bi * 28800;

    for (int i = tid; i < 8 * 196; i += 288) xs[i] = 0.f;   // zero borders once

    for (int c0 = 0; c0 < 200; c0 += 8) {
        __syncthreads();
        for (int i = tid; i < 8 * 144; i += 288) {
            int ic = i / 144, pos = i - ic * 144;
            int y = pos / 12, xx = pos - y * 12;
            xs[ic * 196 + (y + 1) * 14 + xx + 1] = xb[c0 * 144 + i];
        }
        for (int i = tid; i < 8 * 288; i += 288) {
            int ic = i / 288, r = i - ic * 288;
            int k = r >> 5, oc = r & 31;
            ws[i] = w1[oc * 1800 + (c0 + ic) * 9 + k];
        }
        __syncthreads();
#pragma unroll 1
        for (int ic = 0; ic < 8; ic++) {
            float xv[3][6];
            const float* xp = &xs[ic * 196 + py * 14 + px0];
#pragma unroll
            for (int rr = 0; rr < 3; rr++)
#pragma unroll
                for (int cc = 0; cc < 6; cc++) xv[rr][cc] = xp[rr * 14 + cc];
#pragma unroll
            for (int k = 0; k < 9; k++) {
                float4 wv = *(const float4*)&ws[ic * 288 + k * 32 + ocg * 4];
                int rr = k / 3, cc = k % 3;
#pragma unroll
                for (int q = 0; q < 4; q++) {
                    float xvv = xv[rr][cc + q];
                    acc[0][q] += wv.x * xvv;
                    acc[1][q] += wv.y * xvv;
                    acc[2][q] += wv.z * xvv;
                    acc[3][q] += wv.w * xvv;
                }
            }
        }
    }
#pragma unroll
    for (int o = 0; o < 4; o++) {
        int oc = ocg * 4 + o;
        float inv = g1[oc] * rsqrtf(v1[oc] + 1e-5f);
        float sh = (b1[oc] - m1[oc]) * inv + be1[oc];
        float4 v;
        v.x = fmaxf(acc[o][0] * inv + sh, 0.f);
        v.y = fmaxf(acc[o][1] * inv + sh, 0.f);
        v.z = fmaxf(acc[o][2] * inv + sh, 0.f);
        v.w = fmaxf(acc[o][3] * inv + sh, 0.f);
        *(float4*)&g_h1[(size_t)bi * 4608 + oc * 144 + py * 12 + px0] = v;
    }
}

// ============ kernel 2: conv2+BN+ReLU -> we -> wc2 -> in_w ============
// arena floats (28160 total = 112640 B):
//   phase A: ws2[0,4608) [ic][tap][64oc], img[4608,10880) padded 32x196, h2@18688 stride148
//   phase B: we-stage[0,9216), h3@9216 stride148, h2@18688
//   phase C: wc2T[0,4096), h3@9216, h4@18688 stride148
//   phase D: in_w stage[0,9216), h4@18688
__global__ void __launch_bounds__(288, 2) k_mid(
    const float* __restrict__ w2, const float* __restrict__ b2,
    const float* __restrict__ g2, const float* __restrict__ be2,
    const float* __restrict__ m2, const float* __restrict__ v2,
    const float* __restrict__ wc2, const float* __restrict__ bc2,
    const float* __restrict__ we, const float* __restrict__ bee,
    const float* __restrict__ in_w)
{
    extern __shared__ float sm[];
    float* ws2 = sm;
    float* img = sm + 4608;
    float* stage = sm;
    float* h3 = sm + 9216;
    float* h2 = sm + 18688;
    float* h4 = sm + 18688;
    int bi = blockIdx.x, tid = threadIdx.x;

    // ---- phase A: conv2(32->64,3x3)+BN+ReLU ----
    for (int i = tid; i < 32 * 196; i += 288) img[i] = 0.f;
    __syncthreads();
    for (int i = tid; i < 4608; i += 288) {
        int ic = i / 144, pos = i - ic * 144;
        int y = pos / 12, xx = pos - y * 12;
        img[ic * 196 + (y + 1) * 14 + xx + 1] = g_h1[(size_t)bi * 4608 + i];
    }
    {
        int quad = tid % 36, ocg = tid / 36;
        int py = quad / 3, px0 = (quad % 3) * 4;
        float acc[8][4] = {};
        for (int c0 = 0; c0 < 32; c0 += 8) {
            __syncthreads();
            for (int i = tid; i < 8 * 576; i += 288) {
                int ic = i / 576, r = i - ic * 576;
                int k = r >> 6, oc = r & 63;
                ws2[i] = w2[oc * 288 + (c0 + ic) * 9 + k];
            }
            __syncthreads();
#pragma unroll 1
            for (int ic = 0; ic < 8; ic++) {
                float xv[3][6];
                const float* xp = &img[(c0 + ic) * 196 + py * 14 + px0];
#pragma unroll
                for (int rr = 0; rr < 3; rr++)
#pragma unroll
                    for (int cc = 0; cc < 6; cc++) xv[rr][cc] = xp[rr * 14 + cc];
#pragma unroll
                for (int k = 0; k < 9; k++) {
                    float4 w0 = *(const float4*)&ws2[ic * 576 + k * 64 + ocg * 8];
                    float4 w1v = *(const float4*)&ws2[ic * 576 + k * 64 + ocg * 8 + 4];
                    int rr = k / 3, cc = k % 3;
#pragma unroll
                    for (int q = 0; q < 4; q++) {
                        float xvv = xv[rr][cc + q];
                        acc[0][q] += w0.x * xvv; acc[1][q] += w0.y * xvv;
                        acc[2][q] += w0.z * xvv; acc[3][q] += w0.w * xvv;
                        acc[4][q] += w1v.x * xvv; acc[5][q] += w1v.y * xvv;
                        acc[6][q] += w1v.z * xvv; acc[7][q] += w1v.w * xvv;
                    }
                }
            }
        }
#pragma unroll
        for (int o = 0; o < 8; o++) {
            int oc = ocg * 8 + o;
            float inv = g2[oc] * rsqrtf(v2[oc] + 1e-5f);
            float sh = (b2[oc] - m2[oc]) * inv + be2[oc];
#pragma unroll
            for (int q = 0; q < 4; q++)
                h2[oc * 148 + py * 12 + px0 + q] = fmaxf(acc[o][q] * inv + sh, 0.f);
        }
    }

    // ---- phase B: h3 = h2 @ we^T + bee ----
    for (int i0 = 0; i0 < 144; i0 += 64) {
        int ci = (144 - i0) < 64 ? (144 - i0) : 64;
        __syncthreads();
        for (int i = tid; i < ci * 144; i += 288)
            stage[i] = we[(i0 + i / 144) * 144 + (i % 144)];
        __syncthreads();
        int nt = 16 * (ci / 4);
        for (int tile = tid; tile < nt; tile += 288) {
            int t0 = (tile & 15) * 4, ii0 = (tile >> 4) * 4;
            float a[4][4] = {};
            for (int j = 0; j < 144; j += 4) {
                float4 hv[4], wv[4];
#pragma unroll
                for (int r = 0; r < 4; r++) hv[r] = *(const float4*)&h2[(t0 + r) * 148 + j];
#pragma unroll
                for (int c = 0; c < 4; c++) wv[c] = *(const float4*)&stage[(ii0 + c) * 144 + j];
#pragma unroll
                for (int r = 0; r < 4; r++)
#pragma unroll
                    for (int c = 0; c < 4; c++) a[r][c] += d4(hv[r], wv[c]);
            }
#pragma unroll
            for (int r = 0; r < 4; r++)
#pragma unroll
                for (int c = 0; c < 4; c++)
                    h3[(t0 + r) * 148 + i0 + ii0 + c] = a[r][c] + bee[i0 + ii0 + c];
        }
    }

    // ---- phase C: h4 = wc2-mix(h3)+bc2, 4x4 tiles ----
    __syncthreads();
    for (int i = tid; i < 4096; i += 288) {
        int li = i >> 6, lo = i & 63;
        stage[i] = wc2[lo * 64 + li];           // wc2T[li][lo]
    }
    __syncthreads();
    for (int tt = tid; tt < 576; tt += 288) {
        int pt = tt % 36, lt = tt / 36;
        int p0 = pt * 4, lo0 = lt * 4;
        float a[4][4] = {};
        for (int li = 0; li < 64; li++) {
            float4 w4 = *(const float4*)&stage[li * 64 + lo0];
            float4 x4 = *(const float4*)&h3[li * 148 + p0];
            a[0][0] += w4.x * x4.x; a[0][1] += w4.x * x4.y; a[0][2] += w4.x * x4.z; a[0][3] += w4.x * x4.w;
            a[1][0] += w4.y * x4.x; a[1][1] += w4.y * x4.y; a[1][2] += w4.y * x4.z; a[1][3] += w4.y * x4.w;
            a[2][0] += w4.z * x4.x; a[2][1] += w4.z * x4.y; a[2][2] += w4.z * x4.z; a[2][3] += w4.z * x4.w;
            a[3][0] += w4.w * x4.x; a[3][1] += w4.w * x4.y; a[3][2] += w4.w * x4.z; a[3][3] += w4.w * x4.w;
        }
#pragma unroll
        for (int r = 0; r < 4; r++) {
            float bb = bc2[lo0 + r];
            float4 st = {a[r][0] + bb, a[r][1] + bb, a[r][2] + bb, a[r][3] + bb};
            *(float4*)&h4[(lo0 + r) * 148 + p0] = st;
            *(float4*)&g_h4[(size_t)bi * 9216 + (lo0 + r) * 144 + p0] = st;
        }
    }

    // ---- phase D: xz = h4 @ in_w^T -> g_xz ----
    for (int o0 = 0; o0 < 576; o0 += 64) {
        __syncthreads();
        for (int i = tid; i < 64 * 144; i += 288)
            stage[i] = in_w[(o0 + i / 144) * 144 + (i % 144)];
        __syncthreads();
        for (int tile = tid; tile < 256; tile += 288) {
            int t0 = (tile & 15) * 4, oo0 = (tile >> 4) * 4;
            float a[4][4] = {};
            for (int j = 0; j < 144; j += 4) {
                float4 hv[4], wv[4];
#pragma unroll
                for (int r = 0; r < 4; r++) hv[r] = *(const float4*)&h4[(t0 + r) * 148 + j];
#pragma unroll
                for (int c = 0; c < 4; c++) wv[c] = *(const float4*)&stage[(oo0 + c) * 144 + j];
#pragma unroll
                for (int r = 0; r < 4; r++)
#pragma unroll
                    for (int c = 0; c < 4; c++) a[r][c] += d4(hv[r], wv[c]);
            }
#pragma unroll
            for (int r = 0; r < 4; r++) {
                float4 st = {a[r][0], a[r][1], a[r][2], a[r][3]};
                *(float4*)&g_xz[(size_t)bi * 36864 + (t0 + r) * 576 + o0 + oo0] = st;
            }
        }
    }
}

// ============ kernel 3: mamba + residual + wc3 + BN + ReLU ============
// arena: uY[0,18432), dbl[18432,21504), rS[18432,27648), wc3T in uY[0,2048)
__global__ void __launch_bounds__(288, 2) k_mamba(
    const float* __restrict__ convd_w, const float* __restrict__ convd_b,
    const float* __restrict__ xproj_w, const float* __restrict__ dtproj_w,
    const float* __restrict__ dtproj_b, const float* __restrict__ A_log,
    const float* __restrict__ Dp, const float* __restrict__ out_w,
    const float* __restrict__ wc3, const float* __restrict__ bc3,
    const float* __restrict__ g3, const float* __restrict__ be3,
    const float* __restrict__ m3, const float* __restrict__ v3,
    float* __restrict__ out)
{
    extern __shared__ float sm[];
    float* uY = sm;
    float* dbl = sm + 18432;
    float* rS = sm + 18432;
    int bi = blockIdx.x, c = threadIdx.x;
    const float* xzb = g_xz + (size_t)bi * 36864;

    {
        const float4* src = (const float4*)xzb;
        float4* dst = (float4*)uY;
        for (int i = c; i < 4608; i += 288) {
            int t = i / 72, ch4 = i - t * 72;
            dst[t * 72 + ch4] = src[t * 144 + ch4];
        }
    }
    __syncthreads();

    // depthwise causal conv (DC=4) + SiLU, in place, thread=channel
    {
        float cw0 = convd_w[c * 4], cw1 = convd_w[c * 4 + 1],
              cw2 = convd_w[c * 4 + 2], cw3 = convd_w[c * 4 + 3];
        float cb = convd_b[c];
        float p0 = 0.f, p1 = 0.f, p2 = 0.f;
        for (int t = 0; t < 64; t++) {
            float xt = uY[t * 288 + c];
            float s = cw0 * p0 + cw1 * p1 + cw2 * p2 + cw3 * xt + cb;
            s = s / (1.f + __expf(-s));
            uY[t * 288 + c] = s;
            p0 = p1; p1 = p2; p2 = xt;
        }
    }
    __syncthreads();

    // xproj: dbl[t][j] = u[t].xproj_w[j], 4x4 tiles (16 t-tiles x 11 j-tiles)
    if (c < 176) {
        int tt = c & 15, jt = c >> 4;
        int t0 = tt * 4, j0 = jt * 4;
        float a[4][4] = {};
        for (int k = 0; k < 72; k++) {
            float4 uv[4], wv[4];
#pragma unroll
            for (int r = 0; r < 4; r++) uv[r] = *(const float4*)&uY[(t0 + r) * 288 + k * 4];
#pragma unroll
            for (int cc = 0; cc < 4; cc++) {
                int j = j0 + cc; if (j > 40) j = 40;
                wv[cc] = __ldg((const float4*)&xproj_w[j * 288 + k * 4]);
            }
#pragma unroll
            for (int r = 0; r < 4; r++)
#pragma unroll
                for (int cc = 0; cc < 4; cc++) a[r][cc] += d4(uv[r], wv[cc]);
        }
#pragma unroll
        for (int r = 0; r < 4; r++)
#pragma unroll
            for (int cc = 0; cc < 4; cc++)
                if (j0 + cc < 41) dbl[(t0 + r) * 48 + j0 + cc] = a[r][cc];
    }
    __syncthreads();

    // selective scan + gate (thread=channel, 16 states in regs)
    {
        float dtw[9], A[16], h[16];
#pragma unroll
        for (int r = 0; r < 9; r++) dtw[r] = dtproj_w[c * 9 + r];
        float dtb = dtproj_b[c];
#pragma unroll
        for (int n = 0; n < 16; n++) { A[n] = -__expf(A_log[c * 16 + n]); h[n] = 0.f; }
        float dpc = Dp[c];
        for (int t = 0; t < 64; t++) {
            float zv = xzb[t * 576 + 288 + c];
            float dt = dtb;
#pragma unroll
            for (int r = 0; r < 9; r++) dt += dbl[t * 48 + r] * dtw[r];
            float delta = fmaxf(dt, 0.f) + log1pf(__expf(-fabsf(dt)));
            float u = uY[t * 288 + c];
            float dlu = delta * u;
            float y = 0.f;
#pragma unroll
            for (int n = 0; n < 16; n++) {
                float e = __expf(delta * A[n]);
                h[n] = h[n] * e + dlu * dbl[t * 48 + 9 + n];
                y += h[n] * dbl[t * 48 + 25 + n];
            }
            float sz = zv / (1.f + __expf(-zv));
            uY[t * 288 + c] = (y + u * dpc) * sz;
        }
    }
    __syncthreads();

    // out-proj + residual -> rS
    for (int tile = c; tile < 576; tile += 288) {
        int t0 = (tile & 15) * 4, i0 = (tile >> 4) * 4;
        float a[4][4] = {};
        const float4* ow = (const float4*)out_w;
        for (int k = 0; k < 72; k++) {
            float4 yv[4], wv[4];
#pragma unroll
            for (int r = 0; r < 4; r++) yv[r] = *(const float4*)&uY[(t0 + r) * 288 + k * 4];
#pragma unroll
            for (int cc = 0; cc < 4; cc++) wv[cc] = __ldg(&ow[(i0 + cc) * 72 + k]);
#pragma unroll
            for (int r = 0; r < 4; r++)
#pragma unroll
                for (int cc = 0; cc < 4; cc++) a[r][cc] += d4(yv[r], wv[cc]);
        }
#pragma unroll
        for (int r = 0; r < 4; r++) {
            float4 res = __ldg((const float4*)&g_h4[(size_t)bi * 9216 + (t0 + r) * 144 + i0]);
            float4 st = {a[r][0] + res.x, a[r][1] + res.y, a[r][2] + res.z, a[r][3] + res.w};
            *(float4*)&rS[(t0 + r) * 144 + i0] = st;
        }
    }
    __syncthreads();

    // wc3 (64->32 token mix) + BN + ReLU -> out, 4x4 tiles
    for (int i = c; i < 2048; i += 288) {
        int li = i >> 5, oc = i & 31;
        uY[i] = wc3[oc * 64 + li];              // wc3T[li][oc]
    }
    __syncthreads();
    {
        int pt = c % 36, ot = c / 36;           // 288 = 8 oc-tiles x 36 p-tiles
        int p0 = pt * 4, oc0 = ot * 4;
        float a[4][4] = {};
        for (int li = 0; li < 64; li++) {
            float4 w4 = *(const float4*)&uY[li * 32 + oc0];
            float4 x4 = *(const float4*)&rS[li * 144 + p0];
            a[0][0] += w4.x * x4.x; a[0][1] += w4.x * x4.y; a[0][2] += w4.x * x4.z; a[0][3] += w4.x * x4.w;
            a[1][0] += w4.y * x4.x; a[1][1] += w4.y * x4.y; a[1][2] += w4.y * x4.z; a[1][3] += w4.y * x4.w;
            a[2][0] += w4.z * x4.x; a[2][1] += w4.z * x4.y; a[2][2] += w4.z * x4.z; a[2][3] += w4.z * x4.w;
            a[3][0] += w4.w * x4.x; a[3][1] += w4.w * x4.y; a[3][2] += w4.w * x4.z; a[3][3] += w4.w * x4.w;
        }
#pragma unroll
        for (int r = 0; r < 4; r++) {
            int oc = oc0 + r;
            float inv = g3[oc] * rsqrtf(v3[oc] + 1e-5f);
            float sh = (bc3[oc] - m3[oc]) * inv + be3[oc];
            float4 st;
            st.x = fmaxf(a[r][0] * inv + sh, 0.f);
            st.y = fmaxf(a[r][1] * inv + sh, 0.f);
            st.z = fmaxf(a[r][2] * inv + sh, 0.f);
            st.w = fmaxf(a[r][3] * inv + sh, 0.f);
            *(float4*)&out[(size_t)bi * 4608 + oc * 144 + p0] = st;
        }
    }
}

extern "C" void kernel_launch(void* const* d_in, const int* in_sizes, int n_in,
                              void* d_out, int out_size)
{
    const float* x       = (const float*)d_in[0];
    const float* w1      = (const float*)d_in[1];
    const float* b1      = (const float*)d_in[2];
    const float* g1      = (const float*)d_in[3];
    const float* be1     = (const float*)d_in[4];
    const float* m1      = (const float*)d_in[5];
    const float* v1      = (const float*)d_in[6];
    const float* w2      = (const float*)d_in[7];
    const float* b2      = (const float*)d_in[8];
    const float* g2      = (const float*)d_in[9];
    const float* be2     = (const float*)d_in[10];
    const float* m2      = (const float*)d_in[11];
    const float* v2      = (const float*)d_in[12];
    const float* wc2     = (const float*)d_in[13];
    const float* bc2     = (const float*)d_in[14];
    const float* we      = (const float*)d_in[15];
    const float* bee     = (const float*)d_in[16];
    const float* in_w    = (const float*)d_in[17];
    const float* convd_w = (const float*)d_in[18];
    const float* convd_b = (const float*)d_in[19];
    const float* xproj_w = (const float*)d_in[20];
    const float* dtproj_w= (const float*)d_in[21];
    const float* dtproj_b= (const float*)d_in[22];
    const float* A_log   = (const float*)d_in[23];
    const float* Dp      = (const float*)d_in[24];
    const float* out_w   = (const float*)d_in[25];
    const float* wc3     = (const float*)d_in[26];
    const float* bc3     = (const float*)d_in[27];
    const float* g3      = (const float*)d_in[28];
    const float* be3     = (const float*)d_in[29];
    const float* m3      = (const float*)d_in[30];
    const float* v3      = (const float*)d_in[31];

    int B = in_sizes[0] / 28800;

    cudaFuncSetAttribute(k_mid, cudaFuncAttributeMaxDynamicSharedMemorySize, 112640);
    cudaFuncSetAttribute(k_mamba, cudaFuncAttributeMaxDynamicSharedMemorySize, 110592);

    k_front<<<B, 288>>>(x, w1, b1, g1, be1, m1, v1);
    k_mid<<<B, 288, 112640>>>(w2, b2, g2, be2, m2, v2, wc2, bc2, we, bee, in_w);
    k_mamba<<<B, 288, 110592>>>(convd_w, convd_b, xproj_w, dtproj_w, dtproj_b,
                                A_log, Dp, out_w, wc3, bc3, g3, be3, m3, v3,
                                (float*)d_out);
}

// round 4
// speedup vs baseline: 1.9553x; 1.5440x over previous
#include <cuda_runtime.h>
#include <math.h>

__device__ float g_h1[(size_t)512 * 32 * 144];
__device__ float g_h4[(size_t)512 * 64 * 144];
__device__ float g_xz[(size_t)512 * 64 * 576];

__device__ __forceinline__ float d4(float4 a, float4 b) {
    return a.x * b.x + a.y * b.y + a.z * b.z + a.w * b.w;
}

// ============ kernel 1: conv1(200->32,3x3,pad1)+BN+ReLU ============
// 2 images per CTA; thread = 2 rows x 4 cols x 4 oc.
__global__ void __launch_bounds__(288, 3) k_front(
    const float* __restrict__ x, const float* __restrict__ w1,
    const float* __restrict__ b1, const float* __restrict__ g1,
    const float* __restrict__ be1, const float* __restrict__ m1,
    const float* __restrict__ v1)
{
    __shared__ float xs[2][8 * 196];
    __shared__ float ws[8 * 288];        // [ic][tap][32oc]
    int tid = threadIdx.x;
    int img = tid / 144, r = tid - img * 144;
    int pg = r % 18, ocg = r / 18;       // 18 posgroups, 8 oc-groups(4oc)
    int ry = (pg / 3) * 2, cx = (pg % 3) * 4;
    size_t bi = (size_t)blockIdx.x * 2;
    float acc[2][4][4] = {};
    for (int i = tid; i < 2 * 1568; i += 288) ((float*)xs)[i] = 0.f;

    for (int c0 = 0; c0 < 200; c0 += 8) {
        __syncthreads();
        for (int i = tid; i < 2304; i += 288) {
            int im = i / 1152, j = i - im * 1152;
            int ic = j / 144, pos = j - ic * 144;
            int y = pos / 12, xx = pos - y * 12;
            xs[im][ic * 196 + (y + 1) * 14 + xx + 1] =
                x[(bi + im) * 28800 + (c0 + ic) * 144 + pos];
        }
        for (int i = tid; i < 2304; i += 288) {
            int ic = i / 288, rr = i - ic * 288;
            ws[i] = w1[(rr & 31) * 1800 + (c0 + ic) * 9 + (rr >> 5)];
        }
        __syncthreads();
#pragma unroll 1
        for (int ic = 0; ic < 8; ic++) {
            float xv[4][6];
            const float* xp = &xs[img][ic * 196 + ry * 14 + cx];
#pragma unroll
            for (int rr = 0; rr < 4; rr++)
#pragma unroll
                for (int cc = 0; cc < 6; cc++) xv[rr][cc] = xp[rr * 14 + cc];
#pragma unroll
            for (int k = 0; k < 9; k++) {
                float4 wv = *(const float4*)&ws[ic * 288 + k * 32 + ocg * 4];
                int kr = k / 3, kc = k % 3;
#pragma unroll
                for (int orow = 0; orow < 2; orow++)
#pragma unroll
                    for (int q = 0; q < 4; q++) {
                        float xvv = xv[orow + kr][kc + q];
                        acc[orow][0][q] += wv.x * xvv;
                        acc[orow][1][q] += wv.y * xvv;
                        acc[orow][2][q] += wv.z * xvv;
                        acc[orow][3][q] += wv.w * xvv;
                    }
            }
        }
    }
#pragma unroll
    for (int o = 0; o < 4; o++) {
        int oc = ocg * 4 + o;
        float inv = g1[oc] * rsqrtf(v1[oc] + 1e-5f);
        float sh = (b1[oc] - m1[oc]) * inv + be1[oc];
#pragma unroll
        for (int orow = 0; orow < 2; orow++) {
            float4 v;
            v.x = fmaxf(acc[orow][o][0] * inv + sh, 0.f);
            v.y = fmaxf(acc[orow][o][1] * inv + sh, 0.f);
            v.z = fmaxf(acc[orow][o][2] * inv + sh, 0.f);
            v.w = fmaxf(acc[orow][o][3] * inv + sh, 0.f);
            *(float4*)&g_h1[(bi + img) * 4608 + oc * 144 + (ry + orow) * 12 + cx] = v;
        }
    }
}

// ============ kernel 2: conv2+BN+ReLU -> we -> wc2 -> in_w ============
// arena 28160 fl: stage[0,..) , h3[9216,18688) stride148, h2/h4[18688,28160) stride148
__global__ void __launch_bounds__(288, 2) k_mid(
    const float* __restrict__ w2, const float* __restrict__ b2,
    const float* __restrict__ g2, const float* __restrict__ be2,
    const float* __restrict__ m2, const float* __restrict__ v2,
    const float* __restrict__ wc2, const float* __restrict__ bc2,
    const float* __restrict__ we, const float* __restrict__ bee,
    const float* __restrict__ in_w)
{
    extern __shared__ float sm[];
    float* ws2 = sm;                 // phase A [ic][tap][64oc] 4608
    float* img = sm + 4608;          // phase A padded 32x196 = 6272
    float* stage = sm;
    float* h3 = sm + 9216;
    float* h2 = sm + 18688;
    float* h4 = sm + 18688;
    int bi = blockIdx.x, tid = threadIdx.x;

    // ---- phase A: conv2(32->64)+BN+ReLU, 144 threads, 2x4x8oc ----
    for (int i = tid; i < 6272; i += 288) img[i] = 0.f;
    __syncthreads();
    for (int i = tid; i < 4608; i += 288) {
        int ic = i / 144, pos = i - ic * 144;
        int y = pos / 12, xx = pos - y * 12;
        img[ic * 196 + (y + 1) * 14 + xx + 1] = g_h1[(size_t)bi * 4608 + i];
    }
    {
        int pg = tid % 18, ocg = (tid / 18) & 7;
        int ry = (pg / 3) * 2, cx = (pg % 3) * 4;
        float acc[2][8][4] = {};
        for (int c0 = 0; c0 < 32; c0 += 8) {
            __syncthreads();
            for (int i = tid; i < 4608; i += 288) {
                int ic = i / 576, rr = i - ic * 576;
                ws2[i] = w2[(rr & 63) * 288 + (c0 + ic) * 9 + (rr >> 6)];
            }
            __syncthreads();
            if (tid < 144) {
#pragma unroll 1
                for (int ic = 0; ic < 8; ic++) {
                    float xv[4][6];
                    const float* xp = &img[(c0 + ic) * 196 + ry * 14 + cx];
#pragma unroll
                    for (int rr = 0; rr < 4; rr++)
#pragma unroll
                        for (int cc = 0; cc < 6; cc++) xv[rr][cc] = xp[rr * 14 + cc];
#pragma unroll
                    for (int k = 0; k < 9; k++) {
                        float4 w0 = *(const float4*)&ws2[ic * 576 + k * 64 + ocg * 8];
                        float4 w1v = *(const float4*)&ws2[ic * 576 + k * 64 + ocg * 8 + 4];
                        int kr = k / 3, kc = k % 3;
#pragma unroll
                        for (int orow = 0; orow < 2; orow++)
#pragma unroll
                            for (int q = 0; q < 4; q++) {
                                float xvv = xv[orow + kr][kc + q];
                                acc[orow][0][q] += w0.x * xvv; acc[orow][1][q] += w0.y * xvv;
                                acc[orow][2][q] += w0.z * xvv; acc[orow][3][q] += w0.w * xvv;
                                acc[orow][4][q] += w1v.x * xvv; acc[orow][5][q] += w1v.y * xvv;
                                acc[orow][6][q] += w1v.z * xvv; acc[orow][7][q] += w1v.w * xvv;
                            }
                    }
                }
            }
        }
        if (tid < 144) {
#pragma unroll
            for (int o = 0; o < 8; o++) {
                int oc = ocg * 8 + o;
                float inv = g2[oc] * rsqrtf(v2[oc] + 1e-5f);
                float sh = (b2[oc] - m2[oc]) * inv + be2[oc];
#pragma unroll
                for (int orow = 0; orow < 2; orow++)
#pragma unroll
                    for (int q = 0; q < 4; q++)
                        h2[oc * 148 + (ry + orow) * 12 + cx + q] =
                            fmaxf(acc[orow][o][q] * inv + sh, 0.f);
            }
        }
    }

    // ---- phase B: h3 = h2 @ we^T + bee (broadcast scheme, 48-o chunks) ----
    {
        int oslot = tid % 48, tc = tid / 48;     // tc 0..3 for tid<192
        const float4* h24 = (const float4*)h2;
        for (int o0 = 0; o0 < 144; o0 += 48) {
            __syncthreads();
            for (int i = tid; i < 48 * 144; i += 288) {
                int o = i / 144, k = i - o * 144;
                stage[o * 148 + k] = we[(o0 + o) * 144 + k];
            }
            __syncthreads();
            if (tid < 192) {
                float acc[16] = {};
                const float4* w4 = (const float4*)&stage[oslot * 148];
                int tb = tc * 16;
                for (int k4 = 0; k4 < 36; k4++) {
                    float4 wv = w4[k4];
#pragma unroll
                    for (int t = 0; t < 16; t++)
                        acc[t] += d4(h24[(tb + t) * 37 + k4], wv);
                }
                float bb = bee[o0 + oslot];
#pragma unroll
                for (int t = 0; t < 16; t++)
                    h3[(tb + t) * 148 + o0 + oslot] = acc[t] + bb;
            }
        }
    }

    // ---- phase C: h4 = wc2-mix(h3)+bc2 (token mix, 4x4 tiles) ----
    __syncthreads();
    for (int i = tid; i < 4096; i += 288) {
        int li = i >> 6, lo = i & 63;
        stage[i] = wc2[lo * 64 + li];
    }
    __syncthreads();
    for (int tt = tid; tt < 576; tt += 288) {
        int pt = tt % 36, lt = tt / 36;
        int p0 = pt * 4, lo0 = lt * 4;
        float a[4][4] = {};
        for (int li = 0; li < 64; li++) {
            float4 w4 = *(const float4*)&stage[li * 64 + lo0];
            float4 x4 = *(const float4*)&h3[li * 148 + p0];
            a[0][0] += w4.x * x4.x; a[0][1] += w4.x * x4.y; a[0][2] += w4.x * x4.z; a[0][3] += w4.x * x4.w;
            a[1][0] += w4.y * x4.x; a[1][1] += w4.y * x4.y; a[1][2] += w4.y * x4.z; a[1][3] += w4.y * x4.w;
            a[2][0] += w4.z * x4.x; a[2][1] += w4.z * x4.y; a[2][2] += w4.z * x4.z; a[2][3] += w4.z * x4.w;
            a[3][0] += w4.w * x4.x; a[3][1] += w4.w * x4.y; a[3][2] += w4.w * x4.z; a[3][3] += w4.w * x4.w;
        }
#pragma unroll
        for (int r = 0; r < 4; r++) {
            float bb = bc2[lo0 + r];
            float4 st = {a[r][0] + bb, a[r][1] + bb, a[r][2] + bb, a[r][3] + bb};
            *(float4*)&h4[(lo0 + r) * 148 + p0] = st;
            *(float4*)&g_h4[(size_t)bi * 9216 + (lo0 + r) * 144 + p0] = st;
        }
    }

    // ---- phase D: xz = h4 @ in_w^T -> g_xz (broadcast, 64-o chunks) ----
    {
        int oslot = tid & 63, tc = tid >> 6;     // tc 0..3 for tid<256
        const float4* h44 = (const float4*)h4;
        for (int o0 = 0; o0 < 576; o0 += 64) {
            __syncthreads();
            for (int i = tid; i < 64 * 144; i += 288) {
                int o = i / 144, k = i - o * 144;
                stage[o * 148 + k] = in_w[(o0 + o) * 144 + k];
            }
            __syncthreads();
            if (tid < 256) {
                float acc[16] = {};
                const float4* w4 = (const float4*)&stage[oslot * 148];
                int tb = tc * 16;
                for (int k4 = 0; k4 < 36; k4++) {
                    float4 wv = w4[k4];
#pragma unroll
                    for (int t = 0; t < 16; t++)
                        acc[t] += d4(h44[(tb + t) * 37 + k4], wv);
                }
#pragma unroll
                for (int t = 0; t < 16; t++)
                    g_xz[(size_t)bi * 36864 + (tb + t) * 576 + o0 + oslot] = acc[t];
            }
        }
    }
}

// ============ kernel 3: mamba + residual + wc3 + BN + ReLU ============
__global__ void __launch_bounds__(288, 2) k_mamba(
    const float* __restrict__ convd_w, const float* __restrict__ convd_b,
    const float* __restrict__ xproj_w, const float* __restrict__ dtproj_w,
    const float* __restrict__ dtproj_b, const float* __restrict__ A_log,
    const float* __restrict__ Dp, const float* __restrict__ out_w,
    const float* __restrict__ wc3, const float* __restrict__ bc3,
    const float* __restrict__ g3, const float* __restrict__ be3,
    const float* __restrict__ m3, const float* __restrict__ v3,
    float* __restrict__ out)
{
    extern __shared__ float sm[];
    float* uY = sm;                  // 18432
    float* dbl = sm + 18432;         // 3072 (overlaid by rS later)
    float* rS = sm + 18432;          // 9216
    int bi = blockIdx.x, c = threadIdx.x;
    const float* xzb = g_xz + (size_t)bi * 36864;

    {
        const float4* src = (const float4*)xzb;
        float4* dst = (float4*)uY;
        for (int i = c; i < 4608; i += 288) {
            int t = i / 72, ch4 = i - t * 72;
            dst[t * 72 + ch4] = src[t * 144 + ch4];
        }
    }
    __syncthreads();

    // depthwise causal conv (DC=4) + SiLU, in place, thread=channel
    {
        float cw0 = convd_w[c * 4], cw1 = convd_w[c * 4 + 1],
              cw2 = convd_w[c * 4 + 2], cw3 = convd_w[c * 4 + 3];
        float cb = convd_b[c];
        float p0 = 0.f, p1 = 0.f, p2 = 0.f;
        for (int t = 0; t < 64; t++) {
            float xt = uY[t * 288 + c];
            float s = cw0 * p0 + cw1 * p1 + cw2 * p2 + cw3 * xt + cb;
            s = s / (1.f + __expf(-s));
            uY[t * 288 + c] = s;
            p0 = p1; p1 = p2; p2 = xt;
        }
    }
    __syncthreads();

    // xproj (broadcast): thread = (tc 0..3, j 0..40), 16 t each
    if (c < 164) {
        int j = c % 41, tc = c / 41;
        float acc[16] = {};
        const float4* xw4 = (const float4*)&xproj_w[j * 288];
        const float4* uY4 = (const float4*)uY;
        int tb = tc * 16;
        float4 wv = __ldg(&xw4[0]);
        for (int k4 = 0; k4 < 72; k4++) {
            float4 wn = (k4 < 71) ? __ldg(&xw4[k4 + 1]) : wv;
#pragma unroll
            for (int t = 0; t < 16; t++)
                acc[t] += d4(uY4[(tb + t) * 72 + k4], wv);
            wv = wn;
        }
#pragma unroll
        for (int t = 0; t < 16; t++) dbl[(tb + t) * 48 + j] = acc[t];
    }
    __syncthreads();

    // selective scan + gate (thread=channel, 16 states in regs)
    {
        float dtw[9], A[16], h[16];
#pragma unroll
        for (int r = 0; r < 9; r++) dtw[r] = dtproj_w[c * 9 + r];
        float dtb = dtproj_b[c];
#pragma unroll
        for (int n = 0; n < 16; n++) { A[n] = -__expf(A_log[c * 16 + n]); h[n] = 0.f; }
        float dpc = Dp[c];
        for (int t = 0; t < 64; t++) {
            float zv = xzb[t * 576 + 288 + c];
            float dt = dtb;
#pragma unroll
            for (int r = 0; r < 9; r++) dt += dbl[t * 48 + r] * dtw[r];
            float delta = fmaxf(dt, 0.f) + log1pf(__expf(-fabsf(dt)));
            float u = uY[t * 288 + c];
            float dlu = delta * u;
            float y = 0.f;
#pragma unroll
            for (int n = 0; n < 16; n++) {
                float e = __expf(delta * A[n]);
                h[n] = h[n] * e + dlu * dbl[t * 48 + 9 + n];
                y += h[n] * dbl[t * 48 + 25 + n];
            }
            float sz = zv / (1.f + __expf(-zv));
            uY[t * 288 + c] = (y + u * dpc) * sz;
        }
    }
    __syncthreads();

    // out-proj (broadcast) + residual -> rS: thread = (tc 0..1, o 0..143), 32 t
    {
        int o = c % 144, tc = c / 144;
        float acc[32] = {};
        const float4* ow4 = (const float4*)&out_w[o * 288];
        const float4* uY4 = (const float4*)uY;
        int tb = tc * 32;
        float4 wv = __ldg(&ow4[0]);
        for (int k4 = 0; k4 < 72; k4++) {
            float4 wn = (k4 < 71) ? __ldg(&ow4[k4 + 1]) : wv;
#pragma unroll
            for (int t = 0; t < 32; t++)
                acc[t] += d4(uY4[(tb + t) * 72 + k4], wv);
            wv = wn;
        }
        const float* resb = g_h4 + (size_t)bi * 9216;
#pragma unroll
        for (int t = 0; t < 32; t++) {
            int tt = tb + t;
            rS[tt * 144 + o] = acc[t] + __ldg(&resb[tt * 144 + o]);
        }
    }
    __syncthreads();

    // wc3 (64->32 token mix) + BN + ReLU -> out, 4x4 tiles
    for (int i = c; i < 2048; i += 288) {
        int li = i >> 5, oc = i & 31;
        uY[i] = wc3[oc * 64 + li];
    }
    __syncthreads();
    {
        int pt = c % 36, ot = c / 36;
        int p0 = pt * 4, oc0 = ot * 4;
        float a[4][4] = {};
        for (int li = 0; li < 64; li++) {
            float4 w4 = *(const float4*)&uY[li * 32 + oc0];
            float4 x4 = *(const float4*)&rS[li * 144 + p0];
            a[0][0] += w4.x * x4.x; a[0][1] += w4.x * x4.y; a[0][2] += w4.x * x4.z; a[0][3] += w4.x * x4.w;
            a[1][0] += w4.y * x4.x; a[1][1] += w4.y * x4.y; a[1][2] += w4.y * x4.z; a[1][3] += w4.y * x4.w;
            a[2][0] += w4.z * x4.x; a[2][1] += w4.z * x4.y; a[2][2] += w4.z * x4.z; a[2][3] += w4.z * x4.w;
            a[3][0] += w4.w * x4.x; a[3][1] += w4.w * x4.y; a[3][2] += w4.w * x4.z; a[3][3] += w4.w * x4.w;
        }
#pragma unroll
        for (int r = 0; r < 4; r++) {
            int oc = oc0 + r;
            float inv = g3[oc] * rsqrtf(v3[oc] + 1e-5f);
            float sh = (bc3[oc] - m3[oc]) * inv + be3[oc];
            float4 st;
            st.x = fmaxf(a[r][0] * inv + sh, 0.f);
            st.y = fmaxf(a[r][1] * inv + sh, 0.f);
            st.z = fmaxf(a[r][2] * inv + sh, 0.f);
            st.w = fmaxf(a[r][3] * inv + sh, 0.f);
            *(float4*)&out[(size_t)bi * 4608 + oc * 144 + p0] = st;
        }
    }
}

extern "C" void kernel_launch(void* const* d_in, const int* in_sizes, int n_in,
                              void* d_out, int out_size)
{
    const float* x       = (const float*)d_in[0];
    const float* w1      = (const float*)d_in[1];
    const float* b1      = (const float*)d_in[2];
    const float* g1      = (const float*)d_in[3];
    const float* be1     = (const float*)d_in[4];
    const float* m1      = (const float*)d_in[5];
    const float* v1      = (const float*)d_in[6];
    const float* w2      = (const float*)d_in[7];
    const float* b2      = (const float*)d_in[8];
    const float* g2      = (const float*)d_in[9];
    const float* be2     = (const float*)d_in[10];
    const float* m2      = (const float*)d_in[11];
    const float* v2      = (const float*)d_in[12];
    const float* wc2     = (const float*)d_in[13];
    const float* bc2     = (const float*)d_in[14];
    const float* we      = (const float*)d_in[15];
    const float* bee     = (const float*)d_in[16];
    const float* in_w    = (const float*)d_in[17];
    const float* convd_w = (const float*)d_in[18];
    const float* convd_b = (const float*)d_in[19];
    const float* xproj_w = (const float*)d_in[20];
    const float* dtproj_w= (const float*)d_in[21];
    const float* dtproj_b= (const float*)d_in[22];
    const float* A_log   = (const float*)d_in[23];
    const float* Dp      = (const float*)d_in[24];
    const float* out_w   = (const float*)d_in[25];
    const float* wc3     = (const float*)d_in[26];
    const float* bc3     = (const float*)d_in[27];
    const float* g3      = (const float*)d_in[28];
    const float* be3     = (const float*)d_in[29];
    const float* m3      = (const float*)d_in[30];
    const float* v3      = (const float*)d_in[31];

    int B = in_sizes[0] / 28800;

    cudaFuncSetAttribute(k_mid, cudaFuncAttributeMaxDynamicSharedMemorySize, 112640);
    cudaFuncSetAttribute(k_mamba, cudaFuncAttributeMaxDynamicSharedMemorySize, 110592);

    k_front<<<B / 2, 288>>>(x, w1, b1, g1, be1, m1, v1);
    k_mid<<<B, 288, 112640>>>(w2, b2, g2, be2, m2, v2, wc2, bc2, we, bee, in_w);
    k_mamba<<<B, 288, 110592>>>(convd_w, convd_b, xproj_w, dtproj_w, dtproj_b,
                                A_log, Dp, out_w, wc3, bc3, g3, be3, m3, v3,
                                (float*)d_out);
}